// round 1
// baseline (speedup 1.0000x reference)
#include <cuda_runtime.h>
#include <math.h>

#define L  384
#define D  128
#define H  128
#define LL (L * L)   // 147456

// Scratch (no cudaMalloc allowed) — static device globals.
__device__ float g_LhT[(size_t)H * LL];   // [h][i*L+k]
__device__ float g_RhT[(size_t)H * LL];   // [h][k*L+j]
__device__ float g_updT[(size_t)H * LL];  // [h][i*L+j]
__device__ float g_WoT[D * H];            // [h][d] = W_out[d][h]

// ---------------------------------------------------------------------------
// Kernel 0: transpose W_out [D,H] -> g_WoT [H,D] so the final GEMM's B loads
// are coalesced.
// ---------------------------------------------------------------------------
__global__ __launch_bounds__(256) void k_wt(const float* __restrict__ Wo) {
    int idx = blockIdx.x * 256 + threadIdx.x;   // 64 blocks * 256 = 16384
    int h = idx >> 7;
    int d = idx & 127;
    g_WoT[h * D + d] = Wo[d * H + h];
}

// ---------------------------------------------------------------------------
// Kernel 1: projection GEMM.
//   C[pair][n] = sum_d P[pair][d] * W[n][d],   n in [0,256): n<128 -> W_left,
//   else W_right. Then mask and scatter transposed into g_LhT / g_RhT.
// Tiles: BM=64 pairs, BN=64 outputs, BK=16. 256 threads, 4x4 per thread.
// ---------------------------------------------------------------------------
__global__ __launch_bounds__(256) void k_proj(
    const float* __restrict__ P, const float* __restrict__ mask,
    const float* __restrict__ Wl, const float* __restrict__ Wr)
{
    __shared__ __align__(16) float As[16][64];
    __shared__ __align__(16) float Bs[16][64];
    __shared__ float Cs[64][65];
    __shared__ float mLs[64];
    __shared__ float mRs[64];

    const int tid = threadIdx.x;
    const int tx = tid & 15;
    const int ty = tid >> 4;
    const int rowBase = blockIdx.x * 64;        // pair tile
    const int colBase = blockIdx.y * 64;        // output-column tile (0..255)
    const bool isL = (colBase < 128);
    const float* __restrict__ W = isL ? Wl : Wr;
    const int hBase = colBase & 127;

    if (tid < 64) {
        int pair = rowBase + tid;
        int r = pair / L;
        int c = pair - r * L;
        mLs[tid] = mask[pair];          // pair_mask[r][c]
        mRs[tid] = mask[c * L + r];     // pair_mask[c][r]  (mT at (k=r, j=c))
    }

    float acc[4][4];
#pragma unroll
    for (int u = 0; u < 4; u++)
#pragma unroll
        for (int v = 0; v < 4; v++) acc[u][v] = 0.f;

    for (int k0 = 0; k0 < D; k0 += 16) {
#pragma unroll
        for (int i = tid; i < 64 * 16; i += 256) {
            int m = i >> 4, k = i & 15;
            As[k][m] = P[(size_t)(rowBase + m) * D + k0 + k];
        }
#pragma unroll
        for (int i = tid; i < 64 * 16; i += 256) {
            int n = i >> 4, k = i & 15;
            Bs[k][n] = W[(hBase + n) * D + k0 + k];
        }
        __syncthreads();
#pragma unroll
        for (int k = 0; k < 16; k++) {
            float a[4], b[4];
            *(float4*)a = *(const float4*)&As[k][ty * 4];
            *(float4*)b = *(const float4*)&Bs[k][tx * 4];
#pragma unroll
            for (int u = 0; u < 4; u++)
#pragma unroll
                for (int v = 0; v < 4; v++)
                    acc[u][v] = fmaf(a[u], b[v], acc[u][v]);
        }
        __syncthreads();
    }

    // Stage transposed in shared, then coalesced scatter (C^T layout).
#pragma unroll
    for (int u = 0; u < 4; u++)
#pragma unroll
        for (int v = 0; v < 4; v++)
            Cs[tx * 4 + v][ty * 4 + u] = acc[u][v];
    __syncthreads();

    float* __restrict__ dst = isL ? g_LhT : g_RhT;
    const float* ms = isL ? mLs : mRs;
#pragma unroll
    for (int i = tid; i < 64 * 64; i += 256) {
        int n = i >> 6, m = i & 63;
        dst[(size_t)(hBase + n) * LL + rowBase + m] = Cs[n][m] * ms[m];
    }
}

// ---------------------------------------------------------------------------
// Kernel 2: triangle einsum as 128 batched GEMMs:
//   updT[h] (384x384) = LhT[h] (384x384, row-major [i][k])
//                     @ RhT[h] (384x384, row-major [k][j])
// Tiles: 64x64, BK=16. 256 threads, 4x4 per thread.
// ---------------------------------------------------------------------------
__global__ __launch_bounds__(256) void k_tri() {
    __shared__ __align__(16) float As[16][64];
    __shared__ __align__(16) float Bs[16][64];

    const int tid = threadIdx.x;
    const int tx = tid & 15;
    const int ty = tid >> 4;
    const int h  = blockIdx.z;
    const int i0 = blockIdx.y * 64;
    const int j0 = blockIdx.x * 64;

    const float* __restrict__ A = g_LhT + (size_t)h * LL;
    const float* __restrict__ B = g_RhT + (size_t)h * LL;
    float* __restrict__ C = g_updT + (size_t)h * LL;

    float acc[4][4];
#pragma unroll
    for (int u = 0; u < 4; u++)
#pragma unroll
        for (int v = 0; v < 4; v++) acc[u][v] = 0.f;

    for (int k0 = 0; k0 < L; k0 += 16) {
#pragma unroll
        for (int i = tid; i < 64 * 16; i += 256) {
            int m = i >> 4, k = i & 15;
            As[k][m] = A[(i0 + m) * L + k0 + k];
        }
#pragma unroll
        for (int i = tid; i < 64 * 16; i += 256) {
            int k = i >> 6, n = i & 63;
            Bs[k][n] = B[(k0 + k) * L + j0 + n];
        }
        __syncthreads();
#pragma unroll
        for (int k = 0; k < 16; k++) {
            float a[4], b[4];
            *(float4*)a = *(const float4*)&As[k][ty * 4];
            *(float4*)b = *(const float4*)&Bs[k][tx * 4];
#pragma unroll
            for (int u = 0; u < 4; u++)
#pragma unroll
                for (int v = 0; v < 4; v++)
                    acc[u][v] = fmaf(a[u], b[v], acc[u][v]);
        }
        __syncthreads();
    }

#pragma unroll
    for (int u = 0; u < 4; u++) {
        float4 r = make_float4(acc[u][0], acc[u][1], acc[u][2], acc[u][3]);
        *(float4*)&C[(size_t)(i0 + ty * 4 + u) * L + j0 + tx * 4] = r;
    }
}

// ---------------------------------------------------------------------------
// Kernel 3: output projection + residual + mask + LayerNorm, fused.
//   upd2[pair][d] = sum_h updT[h][pair] * WoT[h][d]
//   Pn = P + mask*upd2 ;  out = LN(Pn)*gamma + beta
// Tiles: BM=64 pairs, BN=128 (all of d), BK=16 over h. 256 threads,
// per-thread 4 pairs x 8 d. The 16 lanes tx=0..15 of a half-warp jointly
// hold a full d-row -> LayerNorm via width-16 shuffles.
// ---------------------------------------------------------------------------
__global__ __launch_bounds__(256) void k_fin(
    const float* __restrict__ P, const float* __restrict__ mask,
    const float* __restrict__ gamma, const float* __restrict__ beta,
    float* __restrict__ out)
{
    __shared__ __align__(16) float As[16][64];
    __shared__ __align__(16) float Bs[16][128];

    const int tid = threadIdx.x;
    const int tx = tid & 15;        // d group: d = tx*8 .. tx*8+7
    const int ty = tid >> 4;        // pair group: pair = ty*4 .. ty*4+3
    const int pairBase = blockIdx.x * 64;

    float acc[4][8];
#pragma unroll
    for (int u = 0; u < 4; u++)
#pragma unroll
        for (int v = 0; v < 8; v++) acc[u][v] = 0.f;

    for (int k0 = 0; k0 < H; k0 += 16) {
#pragma unroll
        for (int i = tid; i < 64 * 16; i += 256) {
            int kh = i >> 6, m = i & 63;
            As[kh][m] = g_updT[(size_t)(k0 + kh) * LL + pairBase + m];
        }
#pragma unroll
        for (int i = tid; i < 128 * 16; i += 256) {
            int kh = i >> 7, d = i & 127;
            Bs[kh][d] = g_WoT[(k0 + kh) * D + d];
        }
        __syncthreads();
#pragma unroll
        for (int kh = 0; kh < 16; kh++) {
            float a[4], b[8];
            *(float4*)a       = *(const float4*)&As[kh][ty * 4];
            *(float4*)&b[0]   = *(const float4*)&Bs[kh][tx * 8];
            *(float4*)&b[4]   = *(const float4*)&Bs[kh][tx * 8 + 4];
#pragma unroll
            for (int u = 0; u < 4; u++)
#pragma unroll
                for (int v = 0; v < 8; v++)
                    acc[u][v] = fmaf(a[u], b[v], acc[u][v]);
        }
        __syncthreads();
    }

    // gamma/beta for this thread's 8 d's
    float g[8], bb[8];
    *(float4*)&g[0]  = *(const float4*)&gamma[tx * 8];
    *(float4*)&g[4]  = *(const float4*)&gamma[tx * 8 + 4];
    *(float4*)&bb[0] = *(const float4*)&beta[tx * 8];
    *(float4*)&bb[4] = *(const float4*)&beta[tx * 8 + 4];

#pragma unroll
    for (int u = 0; u < 4; u++) {
        int pair = pairBase + ty * 4 + u;
        float mk = mask[pair];
        float pn[8];
        float4 p0 = *(const float4*)&P[(size_t)pair * D + tx * 8];
        float4 p1 = *(const float4*)&P[(size_t)pair * D + tx * 8 + 4];
        pn[0] = p0.x + mk * acc[u][0];
        pn[1] = p0.y + mk * acc[u][1];
        pn[2] = p0.z + mk * acc[u][2];
        pn[3] = p0.w + mk * acc[u][3];
        pn[4] = p1.x + mk * acc[u][4];
        pn[5] = p1.y + mk * acc[u][5];
        pn[6] = p1.z + mk * acc[u][6];
        pn[7] = p1.w + mk * acc[u][7];

        float s = 0.f, sq = 0.f;
#pragma unroll
        for (int v = 0; v < 8; v++) { s += pn[v]; sq += pn[v] * pn[v]; }
        // reduce across the 16 lanes that share this pair
#pragma unroll
        for (int off = 8; off > 0; off >>= 1) {
            s  += __shfl_down_sync(0xffffffffu, s,  off, 16);
            sq += __shfl_down_sync(0xffffffffu, sq, off, 16);
        }
        s  = __shfl_sync(0xffffffffu, s,  0, 16);
        sq = __shfl_sync(0xffffffffu, sq, 0, 16);

        float mu  = s * (1.f / 128.f);
        float var = sq * (1.f / 128.f) - mu * mu;
        float inv = rsqrtf(var + 1e-5f);

        float o[8];
#pragma unroll
        for (int v = 0; v < 8; v++)
            o[v] = (pn[v] - mu) * inv * g[v] + bb[v];
        *(float4*)&out[(size_t)pair * D + tx * 8]     = *(float4*)&o[0];
        *(float4*)&out[(size_t)pair * D + tx * 8 + 4] = *(float4*)&o[4];
    }
}

// ---------------------------------------------------------------------------
extern "C" void kernel_launch(void* const* d_in, const int* in_sizes, int n_in,
                              void* d_out, int out_size) {
    const float* P     = (const float*)d_in[0];
    const float* mask  = (const float*)d_in[1];
    const float* Wl    = (const float*)d_in[2];
    const float* Wr    = (const float*)d_in[3];
    const float* Wo    = (const float*)d_in[4];
    const float* gamma = (const float*)d_in[5];
    const float* beta  = (const float*)d_in[6];
    float* out = (float*)d_out;

    k_wt<<<64, 256>>>(Wo);
    k_proj<<<dim3(LL / 64, 4), 256>>>(P, mask, Wl, Wr);
    k_tri<<<dim3(L / 64, L / 64, H), 256>>>();
    k_fin<<<LL / 64, 256>>>(P, mask, gamma, beta, out);
}

// round 2
// speedup vs baseline: 3.6052x; 3.6052x over previous
#include <cuda_runtime.h>

#define L  384
#define D  128
#define H  128
#define LL (L * L)   // 147456

// Scratch — static device globals (no cudaMalloc allowed).
__device__ float g_LhT[(size_t)H * LL];   // [h][i*L+k]  (tf32-rounded)
__device__ float g_RhT[(size_t)H * LL];   // [h][k*L+j]  (tf32-rounded)
__device__ float g_updT[(size_t)H * LL];  // [h][i*L+j]  (tf32-rounded)
__device__ float g_WoT[H * D];            // [h][d] = tf32(W_out[d][h])

// ---------------------------------------------------------------------------
// tf32 helpers
// ---------------------------------------------------------------------------
__device__ __forceinline__ unsigned f2tf(float x) {
    unsigned r; asm("cvt.rna.tf32.f32 %0, %1;" : "=r"(r) : "f"(x)); return r;
}
__device__ __forceinline__ float f2tff(float x) { return __uint_as_float(f2tf(x)); }

__device__ __forceinline__ void mma8(float c[4], const unsigned a[4], const unsigned b[2]) {
    asm volatile(
        "mma.sync.aligned.m16n8k8.row.col.f32.tf32.tf32.f32 "
        "{%0,%1,%2,%3}, {%4,%5,%6,%7}, {%8,%9}, {%0,%1,%2,%3};"
        : "+f"(c[0]), "+f"(c[1]), "+f"(c[2]), "+f"(c[3])
        : "r"(a[0]), "r"(a[1]), "r"(a[2]), "r"(a[3]), "r"(b[0]), "r"(b[1]));
}

// ---------------------------------------------------------------------------
// Kernel 0: transpose + tf32-round W_out [D,H] -> g_WoT [H,D]
// ---------------------------------------------------------------------------
__global__ __launch_bounds__(256) void k_wt(const float* __restrict__ Wo) {
    int idx = blockIdx.x * 256 + threadIdx.x;   // 16384
    int h = idx >> 7;
    int d = idx & 127;
    g_WoT[h * D + d] = f2tff(Wo[d * H + h]);
}

// ---------------------------------------------------------------------------
// Kernel 1: projection GEMM (tf32 mma).
//   C[pair][h] = sum_d P[pair][d] * W[h][d];  W = W_left (y=0) / W_right (y=1)
//   Store masked + tf32-rounded, transposed into g_LhT / g_RhT [h][pair].
// Block: 128 pairs x 128 h, BK=32, 8 warps (warp tile 32x64).
// ---------------------------------------------------------------------------
__global__ __launch_bounds__(256) void k_proj(
    const float* __restrict__ P, const float* __restrict__ mask,
    const float* __restrict__ Wl, const float* __restrict__ Wr)
{
    __shared__ __align__(16) float sm[8768];            // 35 KB
#define PAS(k, m) sm[(k) * 137 + (m)]
#define PBS(k, n) sm[32 * 137 + (k) * 137 + (n)]
#define PCS(n, m) sm[(n) * 132 + (m)]
    float* mV = sm + 32 * 132 + 16;                      // 128 mask vals

    const int tid = threadIdx.x;
    const int wid = tid >> 5, lane = tid & 31;
    const int wm = wid & 3, wn = wid >> 2;
    const int group = lane >> 2, tid4 = lane & 3;
    const int pairBase = blockIdx.x * 128;
    const bool isL = (blockIdx.y == 0);
    const float* __restrict__ W = isL ? Wl : Wr;

    float acc[2][8][4];
#pragma unroll
    for (int mt = 0; mt < 2; mt++)
#pragma unroll
        for (int nt = 0; nt < 8; nt++)
#pragma unroll
            for (int v = 0; v < 4; v++) acc[mt][nt][v] = 0.f;

    const int mld = tid >> 3;             // 0..31
    const int kld = (tid & 7) * 4;        // 0..28

    float4 va[4], vb[4];
#pragma unroll
    for (int p = 0; p < 4; p++) {
        va[p] = *(const float4*)&P[(size_t)(pairBase + mld + p * 32) * D + kld];
        vb[p] = *(const float4*)&W[(mld + p * 32) * D + kld];
    }

#pragma unroll
    for (int it = 0; it < 4; it++) {
        __syncthreads();
#pragma unroll
        for (int p = 0; p < 4; p++) {
            int m = mld + p * 32;
            PAS(kld + 0, m) = f2tff(va[p].x);
            PAS(kld + 1, m) = f2tff(va[p].y);
            PAS(kld + 2, m) = f2tff(va[p].z);
            PAS(kld + 3, m) = f2tff(va[p].w);
            PBS(kld + 0, m) = f2tff(vb[p].x);
            PBS(kld + 1, m) = f2tff(vb[p].y);
            PBS(kld + 2, m) = f2tff(vb[p].z);
            PBS(kld + 3, m) = f2tff(vb[p].w);
        }
        __syncthreads();
        if (it < 3) {
            int k0 = (it + 1) * 32;
#pragma unroll
            for (int p = 0; p < 4; p++) {
                va[p] = *(const float4*)&P[(size_t)(pairBase + mld + p * 32) * D + k0 + kld];
                vb[p] = *(const float4*)&W[(mld + p * 32) * D + k0 + kld];
            }
        }
#pragma unroll
        for (int ks = 0; ks < 4; ks++) {
            int k = ks * 8;
            unsigned a[2][4], b[8][2];
#pragma unroll
            for (int mt = 0; mt < 2; mt++) {
                int r = wm * 32 + mt * 16 + group;
                a[mt][0] = __float_as_uint(PAS(k + tid4, r));
                a[mt][1] = __float_as_uint(PAS(k + tid4, r + 8));
                a[mt][2] = __float_as_uint(PAS(k + tid4 + 4, r));
                a[mt][3] = __float_as_uint(PAS(k + tid4 + 4, r + 8));
            }
#pragma unroll
            for (int nt = 0; nt < 8; nt++) {
                int c = wn * 64 + nt * 8 + group;
                b[nt][0] = __float_as_uint(PBS(k + tid4, c));
                b[nt][1] = __float_as_uint(PBS(k + tid4 + 4, c));
            }
#pragma unroll
            for (int mt = 0; mt < 2; mt++)
#pragma unroll
                for (int nt = 0; nt < 8; nt++)
                    mma8(acc[mt][nt], a[mt], b[nt]);
        }
    }

    __syncthreads();
    if (tid < 128) {
        int pair = pairBase + tid;
        int r = pair / L, c = pair - r * L;
        mV[tid] = isL ? mask[pair] : mask[c * L + r];
    }
    float* __restrict__ dst = isL ? g_LhT : g_RhT;

#pragma unroll
    for (int nc = 0; nc < 4; nc++) {
        __syncthreads();
        if (wn == (nc >> 1)) {
#pragma unroll
            for (int nt2 = 0; nt2 < 4; nt2++) {
                int nt = (nc & 1) * 4 + nt2;
                int cc = nt2 * 8 + 2 * tid4;
#pragma unroll
                for (int mt = 0; mt < 2; mt++) {
                    int r = wm * 32 + mt * 16 + group;
                    PCS(cc,     r)     = acc[mt][nt][0];
                    PCS(cc + 1, r)     = acc[mt][nt][1];
                    PCS(cc,     r + 8) = acc[mt][nt][2];
                    PCS(cc + 1, r + 8) = acc[mt][nt][3];
                }
            }
        }
        __syncthreads();
#pragma unroll
        for (int p = 0; p < 4; p++) {
            int nr = (tid >> 5) + p * 8;
            int m  = (tid & 31) * 4;
            float4 o;
            o.x = f2tff(PCS(nr, m + 0) * mV[m + 0]);
            o.y = f2tff(PCS(nr, m + 1) * mV[m + 1]);
            o.z = f2tff(PCS(nr, m + 2) * mV[m + 2]);
            o.w = f2tff(PCS(nr, m + 3) * mV[m + 3]);
            *(float4*)&dst[(size_t)(nc * 32 + nr) * LL + pairBase + m] = o;
        }
    }
#undef PAS
#undef PBS
#undef PCS
}

// ---------------------------------------------------------------------------
// Kernel 2: triangle einsum — 128 batched 384x384x384 GEMMs (tf32 mma).
//   updT[h] = LhT[h] @ RhT[h]
// Block: 128x128, BK=32, 8 warps (32x64 warp tiles), 12 k-iters.
// ---------------------------------------------------------------------------
__global__ __launch_bounds__(256) void k_tri() {
    __shared__ __align__(16) float sm[8736];             // 34.9 KB
#define TAS(k, m) sm[(k) * 137 + (m)]
#define TBS(k, n) sm[4384 + (k) * 136 + (n)]
#define TCS(m, j) sm[(m) * 132 + (j)]

    const int tid = threadIdx.x;
    const int wid = tid >> 5, lane = tid & 31;
    const int wm = wid & 3, wn = wid >> 2;
    const int group = lane >> 2, tid4 = lane & 3;
    const size_t hoff = (size_t)blockIdx.z * LL;
    const int i0 = blockIdx.y * 128;
    const int j0 = blockIdx.x * 128;

    const float* __restrict__ A = g_LhT + hoff;
    const float* __restrict__ B = g_RhT + hoff;

    float acc[2][8][4];
#pragma unroll
    for (int mt = 0; mt < 2; mt++)
#pragma unroll
        for (int nt = 0; nt < 8; nt++)
#pragma unroll
            for (int v = 0; v < 4; v++) acc[mt][nt][v] = 0.f;

    const int mld = tid >> 3;             // A-load: 0..31
    const int kld = (tid & 7) * 4;
    const int kbl = tid >> 5;             // B-load: 0..7
    const int nbl = (tid & 31) * 4;

    float4 va[4], vb[4];
#pragma unroll
    for (int p = 0; p < 4; p++) {
        va[p] = *(const float4*)&A[(size_t)(i0 + mld + p * 32) * L + kld];
        vb[p] = *(const float4*)&B[(size_t)(kbl + p * 8) * L + j0 + nbl];
    }

#pragma unroll 1
    for (int it = 0; it < 12; it++) {
        __syncthreads();
#pragma unroll
        for (int p = 0; p < 4; p++) {
            int m = mld + p * 32;
            TAS(kld + 0, m) = va[p].x;
            TAS(kld + 1, m) = va[p].y;
            TAS(kld + 2, m) = va[p].z;
            TAS(kld + 3, m) = va[p].w;
            *(float4*)&TBS(kbl + p * 8, nbl) = vb[p];
        }
        __syncthreads();
        if (it < 11) {
            int k0 = (it + 1) * 32;
#pragma unroll
            for (int p = 0; p < 4; p++) {
                va[p] = *(const float4*)&A[(size_t)(i0 + mld + p * 32) * L + k0 + kld];
                vb[p] = *(const float4*)&B[(size_t)(k0 + kbl + p * 8) * L + j0 + nbl];
            }
        }
#pragma unroll
        for (int ks = 0; ks < 4; ks++) {
            int k = ks * 8;
            unsigned a[2][4], b[8][2];
#pragma unroll
            for (int mt = 0; mt < 2; mt++) {
                int r = wm * 32 + mt * 16 + group;
                a[mt][0] = __float_as_uint(TAS(k + tid4, r));
                a[mt][1] = __float_as_uint(TAS(k + tid4, r + 8));
                a[mt][2] = __float_as_uint(TAS(k + tid4 + 4, r));
                a[mt][3] = __float_as_uint(TAS(k + tid4 + 4, r + 8));
            }
#pragma unroll
            for (int nt = 0; nt < 8; nt++) {
                int c = wn * 64 + nt * 8 + group;
                b[nt][0] = __float_as_uint(TBS(k + tid4, c));
                b[nt][1] = __float_as_uint(TBS(k + tid4 + 4, c));
            }
#pragma unroll
            for (int mt = 0; mt < 2; mt++)
#pragma unroll
                for (int nt = 0; nt < 8; nt++)
                    mma8(acc[mt][nt], a[mt], b[nt]);
        }
    }

    // Epilogue: two 64-row chunks staged through smem, coalesced tf32 store.
#pragma unroll
    for (int mc = 0; mc < 2; mc++) {
        __syncthreads();
        if ((wm >> 1) == mc) {
#pragma unroll
            for (int nt = 0; nt < 8; nt++) {
                int cc = wn * 64 + nt * 8 + 2 * tid4;
#pragma unroll
                for (int mt = 0; mt < 2; mt++) {
                    int r = (wm & 1) * 32 + mt * 16 + group;
                    TCS(r,     cc)     = acc[mt][nt][0];
                    TCS(r,     cc + 1) = acc[mt][nt][1];
                    TCS(r + 8, cc)     = acc[mt][nt][2];
                    TCS(r + 8, cc + 1) = acc[mt][nt][3];
                }
            }
        }
        __syncthreads();
#pragma unroll
        for (int p = 0; p < 8; p++) {
            int row = (tid >> 5) + p * 8;
            int j   = (tid & 31) * 4;
            float4 o;
            o.x = f2tff(TCS(row, j + 0));
            o.y = f2tff(TCS(row, j + 1));
            o.z = f2tff(TCS(row, j + 2));
            o.w = f2tff(TCS(row, j + 3));
            *(float4*)&g_updT[hoff + (size_t)(i0 + mc * 64 + row) * L + j0 + j] = o;
        }
    }
#undef TAS
#undef TBS
#undef TCS
}

// ---------------------------------------------------------------------------
// Kernel 3: output projection (tf32 mma) + residual + mask + LayerNorm.
// Block: 64 pairs x 128 d, BK=32 over h, 8 warps (16x64 warp tiles).
// ---------------------------------------------------------------------------
__global__ __launch_bounds__(256) void k_fin(
    const float* __restrict__ P, const float* __restrict__ mask,
    const float* __restrict__ gamma, const float* __restrict__ beta,
    float* __restrict__ out)
{
    __shared__ __align__(16) float sm[8704];
#define FAS(k, m) sm[(k) * 136 + (m)]
#define FBS(k, n) sm[4352 + (k) * 136 + (n)]
#define FCS(m, d) sm[(m) * 132 + (d)]

    const int tid = threadIdx.x;
    const int wid = tid >> 5, lane = tid & 31;
    const int wm = wid & 3, wn = wid >> 2;
    const int group = lane >> 2, tid4 = lane & 3;
    const int pairBase = blockIdx.x * 64;

    float acc[8][4];
#pragma unroll
    for (int nt = 0; nt < 8; nt++)
#pragma unroll
        for (int v = 0; v < 4; v++) acc[nt][v] = 0.f;

    const int kal = tid >> 4;             // 0..15
    const int mal = (tid & 15) * 4;       // 0..60
    const int kbl = tid >> 5;             // 0..7
    const int nbl = (tid & 31) * 4;

    float4 va[2], vb[4];
#pragma unroll
    for (int p = 0; p < 2; p++)
        va[p] = *(const float4*)&g_updT[(size_t)(kal + p * 16) * LL + pairBase + mal];
#pragma unroll
    for (int p = 0; p < 4; p++)
        vb[p] = *(const float4*)&g_WoT[(kbl + p * 8) * D + nbl];

#pragma unroll
    for (int it = 0; it < 4; it++) {
        __syncthreads();
#pragma unroll
        for (int p = 0; p < 2; p++)
            *(float4*)&FAS(kal + p * 16, mal) = va[p];
#pragma unroll
        for (int p = 0; p < 4; p++)
            *(float4*)&FBS(kbl + p * 8, nbl) = vb[p];
        __syncthreads();
        if (it < 3) {
            int k0 = (it + 1) * 32;
#pragma unroll
            for (int p = 0; p < 2; p++)
                va[p] = *(const float4*)&g_updT[(size_t)(k0 + kal + p * 16) * LL + pairBase + mal];
#pragma unroll
            for (int p = 0; p < 4; p++)
                vb[p] = *(const float4*)&g_WoT[(k0 + kbl + p * 8) * D + nbl];
        }
#pragma unroll
        for (int ks = 0; ks < 4; ks++) {
            int k = ks * 8;
            unsigned a[4], b[8][2];
            int r = wm * 16 + group;
            a[0] = __float_as_uint(FAS(k + tid4, r));
            a[1] = __float_as_uint(FAS(k + tid4, r + 8));
            a[2] = __float_as_uint(FAS(k + tid4 + 4, r));
            a[3] = __float_as_uint(FAS(k + tid4 + 4, r + 8));
#pragma unroll
            for (int nt = 0; nt < 8; nt++) {
                int c = wn * 64 + nt * 8 + group;
                b[nt][0] = __float_as_uint(FBS(k + tid4, c));
                b[nt][1] = __float_as_uint(FBS(k + tid4 + 4, c));
            }
#pragma unroll
            for (int nt = 0; nt < 8; nt++)
                mma8(acc[nt], a, b[nt]);
        }
    }

    __syncthreads();
#pragma unroll
    for (int nt = 0; nt < 8; nt++) {
        int cc = wn * 64 + nt * 8 + 2 * tid4;
        int r  = wm * 16 + group;
        FCS(r,     cc)     = acc[nt][0];
        FCS(r,     cc + 1) = acc[nt][1];
        FCS(r + 8, cc)     = acc[nt][2];
        FCS(r + 8, cc + 1) = acc[nt][3];
    }
    __syncthreads();

    // LayerNorm: 4 threads per pair-row, 32 d each.
    const int row = tid >> 2;
    const int q   = tid & 3;
    const int pair = pairBase + row;
    const float mk = mask[pair];

    float pn[32];
    float s = 0.f, sq = 0.f;
#pragma unroll
    for (int u = 0; u < 8; u++) {
        float4 pv = *(const float4*)&P[(size_t)pair * D + q * 32 + 4 * u];
        pn[4 * u + 0] = pv.x + mk * FCS(row, q * 32 + 4 * u + 0);
        pn[4 * u + 1] = pv.y + mk * FCS(row, q * 32 + 4 * u + 1);
        pn[4 * u + 2] = pv.z + mk * FCS(row, q * 32 + 4 * u + 2);
        pn[4 * u + 3] = pv.w + mk * FCS(row, q * 32 + 4 * u + 3);
    }
#pragma unroll
    for (int v = 0; v < 32; v++) { s += pn[v]; sq = fmaf(pn[v], pn[v], sq); }
    s  += __shfl_down_sync(0xffffffffu, s,  2, 4);
    s  += __shfl_down_sync(0xffffffffu, s,  1, 4);
    sq += __shfl_down_sync(0xffffffffu, sq, 2, 4);
    sq += __shfl_down_sync(0xffffffffu, sq, 1, 4);
    s  = __shfl_sync(0xffffffffu, s,  0, 4);
    sq = __shfl_sync(0xffffffffu, sq, 0, 4);

    const float mu  = s * (1.f / 128.f);
    const float var = sq * (1.f / 128.f) - mu * mu;
    const float inv = rsqrtf(var + 1e-5f);

#pragma unroll
    for (int u = 0; u < 8; u++) {
        int d = q * 32 + 4 * u;
        float4 gv = *(const float4*)&gamma[d];
        float4 bv = *(const float4*)&beta[d];
        float4 o;
        o.x = (pn[4 * u + 0] - mu) * inv * gv.x + bv.x;
        o.y = (pn[4 * u + 1] - mu) * inv * gv.y + bv.y;
        o.z = (pn[4 * u + 2] - mu) * inv * gv.z + bv.z;
        o.w = (pn[4 * u + 3] - mu) * inv * gv.w + bv.w;
        *(float4*)&out[(size_t)pair * D + d] = o;
    }
#undef FAS
#undef FBS
#undef FCS
}

// ---------------------------------------------------------------------------
extern "C" void kernel_launch(void* const* d_in, const int* in_sizes, int n_in,
                              void* d_out, int out_size) {
    const float* P     = (const float*)d_in[0];
    const float* mask  = (const float*)d_in[1];
    const float* Wl    = (const float*)d_in[2];
    const float* Wr    = (const float*)d_in[3];
    const float* Wo    = (const float*)d_in[4];
    const float* gamma = (const float*)d_in[5];
    const float* beta  = (const float*)d_in[6];
    float* out = (float*)d_out;

    k_wt<<<64, 256>>>(Wo);
    k_proj<<<dim3(LL / 128, 2), 256>>>(P, mask, Wl, Wr);
    k_tri<<<dim3(L / 128, L / 128, H), 256>>>();
    k_fin<<<LL / 64, 256>>>(P, mask, gamma, beta, out);
}

// round 3
// speedup vs baseline: 3.6359x; 1.0085x over previous
#include <cuda_runtime.h>

#define L  384
#define D  128
#define H  128
#define LL (L * L)   // 147456

// Scratch — static device globals (no cudaMalloc allowed).
__device__ float g_LhT[(size_t)H * LL];   // [h][i*L+k]  (tf32-rounded)
__device__ float g_RhT[(size_t)H * LL];   // [h][k*L+j]  (tf32-rounded)
__device__ float g_updT[(size_t)H * LL];  // [h][i*L+j]  (tf32-rounded)
__device__ float g_WoT[H * D];            // [h][d] = tf32(W_out[d][h])

// ---------------------------------------------------------------------------
// helpers
// ---------------------------------------------------------------------------
__device__ __forceinline__ unsigned f2tf(float x) {
    unsigned r; asm("cvt.rna.tf32.f32 %0, %1;" : "=r"(r) : "f"(x)); return r;
}
__device__ __forceinline__ float f2tff(float x) { return __uint_as_float(f2tf(x)); }

__device__ __forceinline__ void mma8(float c[4], const unsigned a[4], const unsigned b[2]) {
    asm volatile(
        "mma.sync.aligned.m16n8k8.row.col.f32.tf32.tf32.f32 "
        "{%0,%1,%2,%3}, {%4,%5,%6,%7}, {%8,%9}, {%0,%1,%2,%3};"
        : "+f"(c[0]), "+f"(c[1]), "+f"(c[2]), "+f"(c[3])
        : "r"(a[0]), "r"(a[1]), "r"(a[2]), "r"(a[3]), "r"(b[0]), "r"(b[1]));
}

__device__ __forceinline__ void cpa16(float* dst, const float* src) {
    unsigned sa = (unsigned)__cvta_generic_to_shared(dst);
    asm volatile("cp.async.cg.shared.global [%0], [%1], 16;" :: "r"(sa), "l"(src));
}
__device__ __forceinline__ void cpa_commit() {
    asm volatile("cp.async.commit_group;");
}
__device__ __forceinline__ void cpa_wait1() {
    asm volatile("cp.async.wait_group 1;");
}

// ---------------------------------------------------------------------------
// Kernel 0: transpose + tf32-round W_out [D,H] -> g_WoT [H,D]
// ---------------------------------------------------------------------------
__global__ __launch_bounds__(256) void k_wt(const float* __restrict__ Wo) {
    int idx = blockIdx.x * 256 + threadIdx.x;   // 16384
    int h = idx >> 7;
    int d = idx & 127;
    g_WoT[h * D + d] = f2tff(Wo[d * H + h]);
}

// ---------------------------------------------------------------------------
// Kernel 1: projection GEMM (tf32 mma) — unchanged from round 2.
// ---------------------------------------------------------------------------
__global__ __launch_bounds__(256) void k_proj(
    const float* __restrict__ P, const float* __restrict__ mask,
    const float* __restrict__ Wl, const float* __restrict__ Wr)
{
    __shared__ __align__(16) float sm[8768];
#define PAS(k, m) sm[(k) * 137 + (m)]
#define PBS(k, n) sm[32 * 137 + (k) * 137 + (n)]
#define PCS(n, m) sm[(n) * 132 + (m)]
    float* mV = sm + 32 * 132 + 16;

    const int tid = threadIdx.x;
    const int wid = tid >> 5, lane = tid & 31;
    const int wm = wid & 3, wn = wid >> 2;
    const int group = lane >> 2, tid4 = lane & 3;
    const int pairBase = blockIdx.x * 128;
    const bool isL = (blockIdx.y == 0);
    const float* __restrict__ W = isL ? Wl : Wr;

    float acc[2][8][4];
#pragma unroll
    for (int mt = 0; mt < 2; mt++)
#pragma unroll
        for (int nt = 0; nt < 8; nt++)
#pragma unroll
            for (int v = 0; v < 4; v++) acc[mt][nt][v] = 0.f;

    const int mld = tid >> 3;
    const int kld = (tid & 7) * 4;

    float4 va[4], vb[4];
#pragma unroll
    for (int p = 0; p < 4; p++) {
        va[p] = *(const float4*)&P[(size_t)(pairBase + mld + p * 32) * D + kld];
        vb[p] = *(const float4*)&W[(mld + p * 32) * D + kld];
    }

#pragma unroll
    for (int it = 0; it < 4; it++) {
        __syncthreads();
#pragma unroll
        for (int p = 0; p < 4; p++) {
            int m = mld + p * 32;
            PAS(kld + 0, m) = f2tff(va[p].x);
            PAS(kld + 1, m) = f2tff(va[p].y);
            PAS(kld + 2, m) = f2tff(va[p].z);
            PAS(kld + 3, m) = f2tff(va[p].w);
            PBS(kld + 0, m) = f2tff(vb[p].x);
            PBS(kld + 1, m) = f2tff(vb[p].y);
            PBS(kld + 2, m) = f2tff(vb[p].z);
            PBS(kld + 3, m) = f2tff(vb[p].w);
        }
        __syncthreads();
        if (it < 3) {
            int k0 = (it + 1) * 32;
#pragma unroll
            for (int p = 0; p < 4; p++) {
                va[p] = *(const float4*)&P[(size_t)(pairBase + mld + p * 32) * D + k0 + kld];
                vb[p] = *(const float4*)&W[(mld + p * 32) * D + k0 + kld];
            }
        }
#pragma unroll
        for (int ks = 0; ks < 4; ks++) {
            int k = ks * 8;
            unsigned a[2][4], b[8][2];
#pragma unroll
            for (int mt = 0; mt < 2; mt++) {
                int r = wm * 32 + mt * 16 + group;
                a[mt][0] = __float_as_uint(PAS(k + tid4, r));
                a[mt][1] = __float_as_uint(PAS(k + tid4, r + 8));
                a[mt][2] = __float_as_uint(PAS(k + tid4 + 4, r));
                a[mt][3] = __float_as_uint(PAS(k + tid4 + 4, r + 8));
            }
#pragma unroll
            for (int nt = 0; nt < 8; nt++) {
                int c = wn * 64 + nt * 8 + group;
                b[nt][0] = __float_as_uint(PBS(k + tid4, c));
                b[nt][1] = __float_as_uint(PBS(k + tid4 + 4, c));
            }
#pragma unroll
            for (int mt = 0; mt < 2; mt++)
#pragma unroll
                for (int nt = 0; nt < 8; nt++)
                    mma8(acc[mt][nt], a[mt], b[nt]);
        }
    }

    __syncthreads();
    if (tid < 128) {
        int pair = pairBase + tid;
        int r = pair / L, c = pair - r * L;
        mV[tid] = isL ? mask[pair] : mask[c * L + r];
    }
    float* __restrict__ dst = isL ? g_LhT : g_RhT;

#pragma unroll
    for (int nc = 0; nc < 4; nc++) {
        __syncthreads();
        if (wn == (nc >> 1)) {
#pragma unroll
            for (int nt2 = 0; nt2 < 4; nt2++) {
                int nt = (nc & 1) * 4 + nt2;
                int cc = nt2 * 8 + 2 * tid4;
#pragma unroll
                for (int mt = 0; mt < 2; mt++) {
                    int r = wm * 32 + mt * 16 + group;
                    PCS(cc,     r)     = acc[mt][nt][0];
                    PCS(cc + 1, r)     = acc[mt][nt][1];
                    PCS(cc,     r + 8) = acc[mt][nt][2];
                    PCS(cc + 1, r + 8) = acc[mt][nt][3];
                }
            }
        }
        __syncthreads();
#pragma unroll
        for (int p = 0; p < 4; p++) {
            int nr = (tid >> 5) + p * 8;
            int m  = (tid & 31) * 4;
            float4 o;
            o.x = f2tff(PCS(nr, m + 0) * mV[m + 0]);
            o.y = f2tff(PCS(nr, m + 1) * mV[m + 1]);
            o.z = f2tff(PCS(nr, m + 2) * mV[m + 2]);
            o.w = f2tff(PCS(nr, m + 3) * mV[m + 3]);
            *(float4*)&dst[(size_t)(nc * 32 + nr) * LL + pairBase + m] = o;
        }
    }
#undef PAS
#undef PBS
#undef PCS
}

// ---------------------------------------------------------------------------
// Kernel 2: triangle einsum — 128 batched 384x384x384 GEMMs (tf32 mma).
// 2-stage cp.async pipeline, BK=16, block 128x128, 8 warps (32x64 tiles).
// A smem [m][k] pitch 20, B smem [k][n] pitch 136 — both conflict-free.
// ---------------------------------------------------------------------------
#define T_STG 4736                    // floats per stage: 128*20 + 16*136
#define TAS(s, m, k) sm[(s) * T_STG + (m) * 20 + (k)]
#define TBS(s, k, n) sm[(s) * T_STG + 2560 + (k) * 136 + (n)]
#define TCS(m, j)    sm[(m) * 132 + (j)]

__global__ __launch_bounds__(256) void k_tri() {
    __shared__ __align__(16) float sm[2 * T_STG];   // 37,888 B

    const int tid = threadIdx.x;
    const int wid = tid >> 5, lane = tid & 31;
    const int wm = wid & 3, wn = wid >> 2;
    const int group = lane >> 2, tid4 = lane & 3;
    const size_t hoff = (size_t)blockIdx.z * LL;
    const int i0 = blockIdx.y * 128;
    const int j0 = blockIdx.x * 128;

    const float* __restrict__ A = g_LhT + hoff;
    const float* __restrict__ B = g_RhT + hoff;

    // load-task coordinates
    const int am = tid >> 1;                 // with p offset -> m in 0..127
    const int aq = (tid & 1) * 2;            // q in {0,2} then +p... (see below)
    const int bk = tid >> 5;                 // 0..7 (+8 with p)
    const int bn4 = (tid & 31) * 4;

    float acc[2][8][4];
#pragma unroll
    for (int mt = 0; mt < 2; mt++)
#pragma unroll
        for (int nt = 0; nt < 8; nt++)
#pragma unroll
            for (int v = 0; v < 4; v++) acc[mt][nt][v] = 0.f;

    // stage loader: 512 float4 for A (128 rows x 4 quads), 512 for B (16 x 32)
#define T_LOAD(s, k0)                                                          \
    {                                                                          \
        _Pragma("unroll")                                                      \
        for (int p = 0; p < 2; p++) {                                          \
            int task = tid + p * 256;                                          \
            int m = task >> 2, q = task & 3;                                   \
            cpa16(&TAS(s, m, q * 4), &A[(size_t)(i0 + m) * L + (k0) + q * 4]); \
        }                                                                      \
        _Pragma("unroll")                                                      \
        for (int p = 0; p < 2; p++) {                                          \
            int task = tid + p * 256;                                          \
            int k = task >> 5, n4 = (task & 31) * 4;                           \
            cpa16(&TBS(s, k, n4), &B[(size_t)((k0) + k) * L + j0 + n4]);       \
        }                                                                      \
    }

    T_LOAD(0, 0);  cpa_commit();
    T_LOAD(1, 16); cpa_commit();

#pragma unroll 2
    for (int it = 0; it < 24; it++) {
        const int s = it & 1;
        cpa_wait1();
        __syncthreads();
#pragma unroll
        for (int ks = 0; ks < 2; ks++) {
            int k = ks * 8;
            unsigned a[2][4], b[8][2];
#pragma unroll
            for (int mt = 0; mt < 2; mt++) {
                int r = wm * 32 + mt * 16 + group;
                a[mt][0] = __float_as_uint(TAS(s, r,     k + tid4));
                a[mt][1] = __float_as_uint(TAS(s, r + 8, k + tid4));
                a[mt][2] = __float_as_uint(TAS(s, r,     k + tid4 + 4));
                a[mt][3] = __float_as_uint(TAS(s, r + 8, k + tid4 + 4));
            }
#pragma unroll
            for (int nt = 0; nt < 8; nt++) {
                int c = wn * 64 + nt * 8 + group;
                b[nt][0] = __float_as_uint(TBS(s, k + tid4,     c));
                b[nt][1] = __float_as_uint(TBS(s, k + tid4 + 4, c));
            }
#pragma unroll
            for (int mt = 0; mt < 2; mt++)
#pragma unroll
                for (int nt = 0; nt < 8; nt++)
                    mma8(acc[mt][nt], a[mt], b[nt]);
        }
        __syncthreads();
        if (it + 2 < 24) T_LOAD(s, (it + 2) * 16);
        cpa_commit();
    }

    // Epilogue: two 64-row chunks staged through smem, coalesced tf32 store.
#pragma unroll
    for (int mc = 0; mc < 2; mc++) {
        __syncthreads();
        if ((wm >> 1) == mc) {
#pragma unroll
            for (int nt = 0; nt < 8; nt++) {
                int cc = wn * 64 + nt * 8 + 2 * tid4;
#pragma unroll
                for (int mt = 0; mt < 2; mt++) {
                    int r = (wm & 1) * 32 + mt * 16 + group;
                    TCS(r,     cc)     = acc[mt][nt][0];
                    TCS(r,     cc + 1) = acc[mt][nt][1];
                    TCS(r + 8, cc)     = acc[mt][nt][2];
                    TCS(r + 8, cc + 1) = acc[mt][nt][3];
                }
            }
        }
        __syncthreads();
#pragma unroll
        for (int p = 0; p < 8; p++) {
            int row = (tid >> 5) + p * 8;
            int j   = (tid & 31) * 4;
            float4 o;
            o.x = f2tff(TCS(row, j + 0));
            o.y = f2tff(TCS(row, j + 1));
            o.z = f2tff(TCS(row, j + 2));
            o.w = f2tff(TCS(row, j + 3));
            *(float4*)&g_updT[hoff + (size_t)(i0 + mc * 64 + row) * L + j0 + j] = o;
        }
    }
#undef T_LOAD
}
#undef TAS
#undef TBS
#undef TCS

// ---------------------------------------------------------------------------
// Kernel 3: output projection (tf32 mma) + residual + mask + LayerNorm.
// Block: 128 pairs x 128 d, BK=16 over h, 2-stage cp.async, 8 warps (32x64).
// ---------------------------------------------------------------------------
#define F_STG 4352                    // floats per stage: 2 * 16*136
#define FAS(s, k, m) sm[(s) * F_STG + (k) * 136 + (m)]
#define FBS(s, k, n) sm[(s) * F_STG + 2176 + (k) * 136 + (n)]
#define FCS(m, d)    sm[(m) * 132 + (d)]

__global__ __launch_bounds__(256) void k_fin(
    const float* __restrict__ P, const float* __restrict__ mask,
    const float* __restrict__ gamma, const float* __restrict__ beta,
    float* __restrict__ out)
{
    __shared__ __align__(16) float sm[2 * F_STG];   // 34,816 B

    const int tid = threadIdx.x;
    const int wid = tid >> 5, lane = tid & 31;
    const int wm = wid & 3, wn = wid >> 2;
    const int group = lane >> 2, tid4 = lane & 3;
    const int pairBase = blockIdx.x * 128;

    float acc[2][8][4];
#pragma unroll
    for (int mt = 0; mt < 2; mt++)
#pragma unroll
        for (int nt = 0; nt < 8; nt++)
#pragma unroll
            for (int v = 0; v < 4; v++) acc[mt][nt][v] = 0.f;

#define F_LOAD(s, k0)                                                              \
    {                                                                              \
        _Pragma("unroll")                                                          \
        for (int p = 0; p < 2; p++) {                                              \
            int task = tid + p * 256;                                              \
            int k = task >> 5, m4 = (task & 31) * 4;                               \
            cpa16(&FAS(s, k, m4), &g_updT[(size_t)((k0) + k) * LL + pairBase + m4]); \
        }                                                                          \
        {                                                                          \
            int k = tid >> 5, n4 = (tid & 31) * 4;                                 \
            cpa16(&FBS(s, k, n4), &g_WoT[((k0) + k) * D + n4]);                    \
            cpa16(&FBS(s, k + 8, n4), &g_WoT[((k0) + k + 8) * D + n4]);            \
        }                                                                          \
    }

    F_LOAD(0, 0);  cpa_commit();
    F_LOAD(1, 16); cpa_commit();

#pragma unroll 2
    for (int it = 0; it < 8; it++) {
        const int s = it & 1;
        cpa_wait1();
        __syncthreads();
#pragma unroll
        for (int ks = 0; ks < 2; ks++) {
            int k = ks * 8;
            unsigned a[2][4], b[8][2];
#pragma unroll
            for (int mt = 0; mt < 2; mt++) {
                int r = wm * 32 + mt * 16 + group;
                a[mt][0] = __float_as_uint(FAS(s, k + tid4,     r));
                a[mt][1] = __float_as_uint(FAS(s, k + tid4,     r + 8));
                a[mt][2] = __float_as_uint(FAS(s, k + tid4 + 4, r));
                a[mt][3] = __float_as_uint(FAS(s, k + tid4 + 4, r + 8));
            }
#pragma unroll
            for (int nt = 0; nt < 8; nt++) {
                int c = wn * 64 + nt * 8 + group;
                b[nt][0] = __float_as_uint(FBS(s, k + tid4,     c));
                b[nt][1] = __float_as_uint(FBS(s, k + tid4 + 4, c));
            }
#pragma unroll
            for (int mt = 0; mt < 2; mt++)
#pragma unroll
                for (int nt = 0; nt < 8; nt++)
                    mma8(acc[mt][nt], a[mt], b[nt]);
        }
        __syncthreads();
        if (it + 2 < 8) F_LOAD(s, (it + 2) * 16);
        cpa_commit();
    }

    // Epilogue: two 64-pair chunks; stage acc -> smem, then LayerNorm.
#pragma unroll
    for (int mc = 0; mc < 2; mc++) {
        __syncthreads();
        if ((wm >> 1) == mc) {
#pragma unroll
            for (int nt = 0; nt < 8; nt++) {
                int cc = wn * 64 + nt * 8 + 2 * tid4;
#pragma unroll
                for (int mt = 0; mt < 2; mt++) {
                    int r = (wm & 1) * 32 + mt * 16 + group;
                    FCS(r,     cc)     = acc[mt][nt][0];
                    FCS(r,     cc + 1) = acc[mt][nt][1];
                    FCS(r + 8, cc)     = acc[mt][nt][2];
                    FCS(r + 8, cc + 1) = acc[mt][nt][3];
                }
            }
        }
        __syncthreads();

        // LayerNorm: 4 threads per pair-row, 32 d each.
        const int row = tid >> 2;
        const int q   = tid & 3;
        const int pair = pairBase + mc * 64 + row;
        const float mk = mask[pair];

        float pn[32];
        float s = 0.f, sq = 0.f;
#pragma unroll
        for (int u = 0; u < 8; u++) {
            float4 pv = *(const float4*)&P[(size_t)pair * D + q * 32 + 4 * u];
            pn[4 * u + 0] = pv.x + mk * FCS(row, q * 32 + 4 * u + 0);
            pn[4 * u + 1] = pv.y + mk * FCS(row, q * 32 + 4 * u + 1);
            pn[4 * u + 2] = pv.z + mk * FCS(row, q * 32 + 4 * u + 2);
            pn[4 * u + 3] = pv.w + mk * FCS(row, q * 32 + 4 * u + 3);
        }
#pragma unroll
        for (int v = 0; v < 32; v++) { s += pn[v]; sq = fmaf(pn[v], pn[v], sq); }
        s  += __shfl_down_sync(0xffffffffu, s,  2, 4);
        s  += __shfl_down_sync(0xffffffffu, s,  1, 4);
        sq += __shfl_down_sync(0xffffffffu, sq, 2, 4);
        sq += __shfl_down_sync(0xffffffffu, sq, 1, 4);
        s  = __shfl_sync(0xffffffffu, s,  0, 4);
        sq = __shfl_sync(0xffffffffu, sq, 0, 4);

        const float mu  = s * (1.f / 128.f);
        const float var = sq * (1.f / 128.f) - mu * mu;
        const float inv = rsqrtf(var + 1e-5f);

#pragma unroll
        for (int u = 0; u < 8; u++) {
            int d = q * 32 + 4 * u;
            float4 gv = *(const float4*)&gamma[d];
            float4 bv = *(const float4*)&beta[d];
            float4 o;
            o.x = (pn[4 * u + 0] - mu) * inv * gv.x + bv.x;
            o.y = (pn[4 * u + 1] - mu) * inv * gv.y + bv.y;
            o.z = (pn[4 * u + 2] - mu) * inv * gv.z + bv.z;
            o.w = (pn[4 * u + 3] - mu) * inv * gv.w + bv.w;
            *(float4*)&out[(size_t)pair * D + d] = o;
        }
    }
#undef F_LOAD
}
#undef FAS
#undef FBS
#undef FCS

// ---------------------------------------------------------------------------
extern "C" void kernel_launch(void* const* d_in, const int* in_sizes, int n_in,
                              void* d_out, int out_size) {
    const float* P     = (const float*)d_in[0];
    const float* mask  = (const float*)d_in[1];
    const float* Wl    = (const float*)d_in[2];
    const float* Wr    = (const float*)d_in[3];
    const float* Wo    = (const float*)d_in[4];
    const float* gamma = (const float*)d_in[5];
    const float* beta  = (const float*)d_in[6];
    float* out = (float*)d_out;

    k_wt<<<64, 256>>>(Wo);
    k_proj<<<dim3(LL / 128, 2), 256>>>(P, mask, Wl, Wr);
    k_tri<<<dim3(L / 128, L / 128, H), 256>>>();
    k_fin<<<LL / 128, 256>>>(P, mask, gamma, beta, out);
}